// round 3
// baseline (speedup 1.0000x reference)
#include <cuda_runtime.h>
#include <math.h>
#include <stdint.h>

#define S_LEN 4096
#define D_MODEL 1024
#define N_HEADS 16
#define D_HEAD 64
#define BK 32

// Scratch (allocation-free rule: __device__ globals)
__device__ float g_Qp[S_LEN * D_MODEL];
__device__ float g_Kp[S_LEN * D_MODEL];
__device__ float g_Vp[S_LEN * D_MODEL];
__device__ float g_vals[S_LEN * D_MODEL];
__device__ float g_part[(size_t)N_HEADS * S_LEN * 32];   // per-(row, nblock) exp partials
__device__ float g_inv[(size_t)N_HEADS * S_LEN];         // 1 / rowsum
__device__ float g_attn_fallback[(size_t)N_HEADS * S_LEN * S_LEN];

__device__ __forceinline__ float to_tf32(float x) {
    float y;
    asm("cvt.rna.tf32.f32 %0, %1;" : "=f"(y) : "f"(x));
    return y;
}

__device__ __forceinline__ void mma_tf32(float& d0, float& d1, float& d2, float& d3,
                                         float a0, float a1, float a2, float a3,
                                         float b0, float b1)
{
    uint32_t ua0 = __float_as_uint(a0), ua1 = __float_as_uint(a1);
    uint32_t ua2 = __float_as_uint(a2), ua3 = __float_as_uint(a3);
    uint32_t ub0 = __float_as_uint(b0), ub1 = __float_as_uint(b1);
    asm volatile(
        "mma.sync.aligned.m16n8k8.row.col.f32.tf32.tf32.f32 "
        "{%0,%1,%2,%3}, {%4,%5,%6,%7}, {%8,%9}, {%0,%1,%2,%3};"
        : "+f"(d0), "+f"(d1), "+f"(d2), "+f"(d3)
        : "r"(ua0), "r"(ua1), "r"(ua2), "r"(ua3), "r"(ub0), "r"(ub1));
}

// ---------------------------------------------------------------------------
// General TF32 GEMM (projections): C = A @ B + bias, B row-major [K, N].
// BM=BN=128, BK=32, 256 threads, 8 warps (4x2), each 32x64.
// ---------------------------------------------------------------------------
__global__ void __launch_bounds__(256, 2)
proj_gemm(const float* __restrict__ A,
          const float* __restrict__ B,
          float* __restrict__ C,
          int K, const float* __restrict__ bias)
{
    __shared__ __align__(16) float As[128][BK + 4];
    __shared__ __align__(16) float Bs[BK][128 + 4];

    const int m0 = blockIdx.y * 128;
    const int n0 = blockIdx.x * 128;
    const int tid = threadIdx.x;
    const int warp = tid >> 5;
    const int lane = tid & 31;
    const int gid = lane >> 2;
    const int tig = lane & 3;
    const int wm0 = (warp >> 1) * 32;
    const int wn0 = (warp & 1) * 64;

    float acc[2][8][4];
    #pragma unroll
    for (int mi = 0; mi < 2; mi++)
        #pragma unroll
        for (int ni = 0; ni < 8; ni++)
            #pragma unroll
            for (int j = 0; j < 4; j++) acc[mi][ni][j] = 0.f;

    for (int k0 = 0; k0 < K; k0 += BK) {
        #pragma unroll
        for (int i = 0; i < 4; i++) {
            int idx = tid + i * 256;
            int r = idx >> 3;
            int kq = (idx & 7) * 4;
            float4 f = *(const float4*)(A + (long)(m0 + r) * K + k0 + kq);
            *(float4*)&As[r][kq] = make_float4(to_tf32(f.x), to_tf32(f.y),
                                               to_tf32(f.z), to_tf32(f.w));
        }
        #pragma unroll
        for (int i = 0; i < 4; i++) {
            int idx = tid + i * 256;
            int kr = idx >> 5;
            int nq = (idx & 31) * 4;
            float4 f = *(const float4*)(B + (long)(k0 + kr) * D_MODEL + n0 + nq);
            *(float4*)&Bs[kr][nq] = make_float4(to_tf32(f.x), to_tf32(f.y),
                                                to_tf32(f.z), to_tf32(f.w));
        }
        __syncthreads();

        #pragma unroll
        for (int ks = 0; ks < BK; ks += 8) {
            float af[2][4];
            #pragma unroll
            for (int mi = 0; mi < 2; mi++) {
                af[mi][0] = As[wm0 + mi * 16 + gid][ks + tig];
                af[mi][1] = As[wm0 + mi * 16 + gid + 8][ks + tig];
                af[mi][2] = As[wm0 + mi * 16 + gid][ks + tig + 4];
                af[mi][3] = As[wm0 + mi * 16 + gid + 8][ks + tig + 4];
            }
            float bf[8][2];
            #pragma unroll
            for (int ni = 0; ni < 8; ni++) {
                bf[ni][0] = Bs[ks + tig][wn0 + ni * 8 + gid];
                bf[ni][1] = Bs[ks + tig + 4][wn0 + ni * 8 + gid];
            }
            #pragma unroll
            for (int mi = 0; mi < 2; mi++)
                #pragma unroll
                for (int ni = 0; ni < 8; ni++)
                    mma_tf32(acc[mi][ni][0], acc[mi][ni][1], acc[mi][ni][2], acc[mi][ni][3],
                             af[mi][0], af[mi][1], af[mi][2], af[mi][3],
                             bf[ni][0], bf[ni][1]);
        }
        __syncthreads();
    }

    #pragma unroll
    for (int mi = 0; mi < 2; mi++) {
        int r0 = m0 + wm0 + mi * 16 + gid;
        #pragma unroll
        for (int ni = 0; ni < 8; ni++) {
            int c = n0 + wn0 + ni * 8 + tig * 2;
            float b0 = bias[c], b1 = bias[c + 1];
            *(float2*)&C[(long)r0 * D_MODEL + c] =
                make_float2(acc[mi][ni][0] + b0, acc[mi][ni][1] + b1);
            *(float2*)&C[(long)(r0 + 8) * D_MODEL + c] =
                make_float2(acc[mi][ni][2] + b0, acc[mi][ni][3] + b1);
        }
    }
}

// ---------------------------------------------------------------------------
// Scores + exp fused: e = exp(scale * Qh @ Kh^T), written to attn.
// Also emits per-(row, nblock) partial sums of e (deterministic reduction).
// Single K=64 shot. Grid: (nb=32, mb=32, h=16).
// ---------------------------------------------------------------------------
__global__ void __launch_bounds__(256, 2)
score_kernel(const float* __restrict__ Qp, const float* __restrict__ Kp,
             float* __restrict__ attn, float* __restrict__ part, float scale)
{
    __shared__ __align__(16) float Qs[128][D_HEAD + 4];
    __shared__ __align__(16) float Ks[128][D_HEAD + 4];
    __shared__ float red[2][128];

    const int nb = blockIdx.x, mb = blockIdx.y, h = blockIdx.z;
    const float* Aq = Qp + (long)mb * 128 * D_MODEL + h * D_HEAD;
    const float* Bk = Kp + (long)nb * 128 * D_MODEL + h * D_HEAD;

    const int tid = threadIdx.x;
    const int warp = tid >> 5;
    const int lane = tid & 31;
    const int gid = lane >> 2;
    const int tig = lane & 3;
    const int wm0 = (warp >> 1) * 32;
    const int wn = warp & 1;
    const int wn0 = wn * 64;

    #pragma unroll
    for (int i = 0; i < 8; i++) {
        int idx = tid + i * 256;
        int r = idx >> 4;
        int c4 = (idx & 15) * 4;
        float4 fq = *(const float4*)(Aq + (long)r * D_MODEL + c4);
        *(float4*)&Qs[r][c4] = make_float4(to_tf32(fq.x), to_tf32(fq.y),
                                           to_tf32(fq.z), to_tf32(fq.w));
        float4 fk = *(const float4*)(Bk + (long)r * D_MODEL + c4);
        *(float4*)&Ks[r][c4] = make_float4(to_tf32(fk.x), to_tf32(fk.y),
                                           to_tf32(fk.z), to_tf32(fk.w));
    }
    __syncthreads();

    float acc[2][8][4];
    #pragma unroll
    for (int mi = 0; mi < 2; mi++)
        #pragma unroll
        for (int ni = 0; ni < 8; ni++)
            #pragma unroll
            for (int j = 0; j < 4; j++) acc[mi][ni][j] = 0.f;

    #pragma unroll
    for (int ks = 0; ks < D_HEAD; ks += 8) {
        float af[2][4];
        #pragma unroll
        for (int mi = 0; mi < 2; mi++) {
            af[mi][0] = Qs[wm0 + mi * 16 + gid][ks + tig];
            af[mi][1] = Qs[wm0 + mi * 16 + gid + 8][ks + tig];
            af[mi][2] = Qs[wm0 + mi * 16 + gid][ks + tig + 4];
            af[mi][3] = Qs[wm0 + mi * 16 + gid + 8][ks + tig + 4];
        }
        float bf[8][2];
        #pragma unroll
        for (int ni = 0; ni < 8; ni++) {
            bf[ni][0] = Ks[wn0 + ni * 8 + gid][ks + tig];
            bf[ni][1] = Ks[wn0 + ni * 8 + gid][ks + tig + 4];
        }
        #pragma unroll
        for (int mi = 0; mi < 2; mi++)
            #pragma unroll
            for (int ni = 0; ni < 8; ni++)
                mma_tf32(acc[mi][ni][0], acc[mi][ni][1], acc[mi][ni][2], acc[mi][ni][3],
                         af[mi][0], af[mi][1], af[mi][2], af[mi][3],
                         bf[ni][0], bf[ni][1]);
    }

    // Epilogue: exp, row partial sums, write e
    float rp[2][2] = {{0.f, 0.f}, {0.f, 0.f}};
    #pragma unroll
    for (int mi = 0; mi < 2; mi++) {
        long r0 = (long)h * S_LEN + mb * 128 + wm0 + mi * 16 + gid;
        #pragma unroll
        for (int ni = 0; ni < 8; ni++) {
            int c = nb * 128 + wn0 + ni * 8 + tig * 2;
            float e0 = __expf(scale * acc[mi][ni][0]);
            float e1 = __expf(scale * acc[mi][ni][1]);
            float e2 = __expf(scale * acc[mi][ni][2]);
            float e3 = __expf(scale * acc[mi][ni][3]);
            rp[mi][0] += e0 + e1;
            rp[mi][1] += e2 + e3;
            *(float2*)&attn[r0 * S_LEN + c] = make_float2(e0, e1);
            *(float2*)&attn[(r0 + 8) * S_LEN + c] = make_float2(e2, e3);
        }
    }
    // reduce across the 4 lanes of each group
    #pragma unroll
    for (int mi = 0; mi < 2; mi++)
        #pragma unroll
        for (int hh = 0; hh < 2; hh++) {
            rp[mi][hh] += __shfl_xor_sync(0xffffffffu, rp[mi][hh], 1);
            rp[mi][hh] += __shfl_xor_sync(0xffffffffu, rp[mi][hh], 2);
        }
    if (tig == 0) {
        #pragma unroll
        for (int mi = 0; mi < 2; mi++)
            #pragma unroll
            for (int hh = 0; hh < 2; hh++)
                red[wn][wm0 + mi * 16 + gid + 8 * hh] = rp[mi][hh];
    }
    __syncthreads();
    if (tid < 128) {
        long row = (long)h * S_LEN + mb * 128 + tid;
        part[row * 32 + nb] = red[0][tid] + red[1][tid];
    }
}

// 1/rowsum from 32 deterministic partials per row
__global__ void invert_kernel(const float* __restrict__ part, float* __restrict__ inv)
{
    long row = blockIdx.x * 256 + threadIdx.x;
    float s = 0.f;
    #pragma unroll
    for (int j = 0; j < 32; j++) s += part[row * 32 + j];
    inv[row] = 1.0f / s;
}

// ---------------------------------------------------------------------------
// AV fused with normalization: reads e, scales by inv[row], writes normalized
// p back in place (each attn element touched exactly once), accumulates
// O = P @ Vh. BM=128, BN=64, BK=32. Grid: (1, mb=32, h=16).
// ---------------------------------------------------------------------------
__global__ void __launch_bounds__(256, 2)
av_kernel(float* __restrict__ attn, const float* __restrict__ inv,
          const float* __restrict__ Vp, float* __restrict__ vals)
{
    __shared__ __align__(16) float As[128][BK + 4];
    __shared__ __align__(16) float Bs[BK][D_HEAD + 4];

    const int mb = blockIdx.y, h = blockIdx.z;
    const long attn_base = ((long)h * S_LEN + mb * 128) * S_LEN;
    const long inv_base = (long)h * S_LEN + mb * 128;

    const int tid = threadIdx.x;
    const int warp = tid >> 5;
    const int lane = tid & 31;
    const int gid = lane >> 2;
    const int tig = lane & 3;
    const int wm0 = (warp >> 1) * 32;
    const int wn0 = (warp & 1) * 32;

    float acc[2][4][4];
    #pragma unroll
    for (int mi = 0; mi < 2; mi++)
        #pragma unroll
        for (int ni = 0; ni < 4; ni++)
            #pragma unroll
            for (int j = 0; j < 4; j++) acc[mi][ni][j] = 0.f;

    for (int k0 = 0; k0 < S_LEN; k0 += BK) {
        // A tile: normalize + write back + stage tf32
        #pragma unroll
        for (int i = 0; i < 4; i++) {
            int idx = tid + i * 256;
            int r = idx >> 3;
            int kq = (idx & 7) * 4;
            float* ga = attn + attn_base + (long)r * S_LEN + k0 + kq;
            float iv = __ldg(inv + inv_base + r);
            float4 f = *(const float4*)ga;
            f.x *= iv; f.y *= iv; f.z *= iv; f.w *= iv;
            *(float4*)ga = f;
            *(float4*)&As[r][kq] = make_float4(to_tf32(f.x), to_tf32(f.y),
                                               to_tf32(f.z), to_tf32(f.w));
        }
        // B tile: V rows k0..k0+31, head cols
        #pragma unroll
        for (int i = 0; i < 2; i++) {
            int idx = tid + i * 256;
            int kr = idx >> 4;
            int nq = (idx & 15) * 4;
            float4 f = *(const float4*)(Vp + (long)(k0 + kr) * D_MODEL + h * D_HEAD + nq);
            *(float4*)&Bs[kr][nq] = make_float4(to_tf32(f.x), to_tf32(f.y),
                                                to_tf32(f.z), to_tf32(f.w));
        }
        __syncthreads();

        #pragma unroll
        for (int ks = 0; ks < BK; ks += 8) {
            float af[2][4];
            #pragma unroll
            for (int mi = 0; mi < 2; mi++) {
                af[mi][0] = As[wm0 + mi * 16 + gid][ks + tig];
                af[mi][1] = As[wm0 + mi * 16 + gid + 8][ks + tig];
                af[mi][2] = As[wm0 + mi * 16 + gid][ks + tig + 4];
                af[mi][3] = As[wm0 + mi * 16 + gid + 8][ks + tig + 4];
            }
            float bf[4][2];
            #pragma unroll
            for (int ni = 0; ni < 4; ni++) {
                bf[ni][0] = Bs[ks + tig][wn0 + ni * 8 + gid];
                bf[ni][1] = Bs[ks + tig + 4][wn0 + ni * 8 + gid];
            }
            #pragma unroll
            for (int mi = 0; mi < 2; mi++)
                #pragma unroll
                for (int ni = 0; ni < 4; ni++)
                    mma_tf32(acc[mi][ni][0], acc[mi][ni][1], acc[mi][ni][2], acc[mi][ni][3],
                             af[mi][0], af[mi][1], af[mi][2], af[mi][3],
                             bf[ni][0], bf[ni][1]);
        }
        __syncthreads();
    }

    #pragma unroll
    for (int mi = 0; mi < 2; mi++) {
        int r0 = mb * 128 + wm0 + mi * 16 + gid;
        #pragma unroll
        for (int ni = 0; ni < 4; ni++) {
            int c = h * D_HEAD + wn0 + ni * 8 + tig * 2;
            *(float2*)&vals[(long)r0 * D_MODEL + c] =
                make_float2(acc[mi][ni][0], acc[mi][ni][1]);
            *(float2*)&vals[(long)(r0 + 8) * D_MODEL + c] =
                make_float2(acc[mi][ni][2], acc[mi][ni][3]);
        }
    }
}

extern "C" void kernel_launch(void* const* d_in, const int* in_sizes, int n_in,
                              void* d_out, int out_size)
{
    const float* q  = (const float*)d_in[0];
    const float* k  = (const float*)d_in[1];
    const float* v  = (const float*)d_in[2];
    const float* Wq = (const float*)d_in[3];
    const float* bq = (const float*)d_in[4];
    const float* Wk = (const float*)d_in[5];
    const float* bk = (const float*)d_in[6];
    const float* Wv = (const float*)d_in[7];
    const float* bv = (const float*)d_in[8];
    const float* Wo = (const float*)d_in[9];
    const float* bo = (const float*)d_in[10];

    float* out = (float*)d_out;

    float *Qp, *Kp, *Vp, *Vals, *Part, *Inv, *attn_fb;
    cudaGetSymbolAddress((void**)&Qp,   g_Qp);
    cudaGetSymbolAddress((void**)&Kp,   g_Kp);
    cudaGetSymbolAddress((void**)&Vp,   g_Vp);
    cudaGetSymbolAddress((void**)&Vals, g_vals);
    cudaGetSymbolAddress((void**)&Part, g_part);
    cudaGetSymbolAddress((void**)&Inv,  g_inv);
    cudaGetSymbolAddress((void**)&attn_fb, g_attn_fallback);

    const long OUT_ELEMS  = (long)S_LEN * D_MODEL;
    const long ATTN_ELEMS = (long)N_HEADS * S_LEN * S_LEN;
    float* attn = ((long)out_size >= OUT_ELEMS + ATTN_ELEMS)
                      ? (out + OUT_ELEMS)
                      : attn_fb;

    dim3 blk(256);
    const float scale = 1.0f / sqrtf((float)D_HEAD);

    // 1) Projections
    dim3 gProj(D_MODEL / 128, S_LEN / 128, 1);
    proj_gemm<<<gProj, blk>>>(q, Wq, Qp, D_MODEL, bq);
    proj_gemm<<<gProj, blk>>>(k, Wk, Kp, D_MODEL, bk);
    proj_gemm<<<gProj, blk>>>(v, Wv, Vp, D_MODEL, bv);

    // 2) Scores + exp + partial row sums
    dim3 gScore(S_LEN / 128, S_LEN / 128, N_HEADS);
    score_kernel<<<gScore, blk>>>(Qp, Kp, attn, Part, scale);

    // 3) 1/rowsum
    invert_kernel<<<(N_HEADS * S_LEN) / 256, 256>>>(Part, Inv);

    // 4) Normalize attn in place + O = P @ V
    dim3 gAV(1, S_LEN / 128, N_HEADS);
    av_kernel<<<gAV, blk>>>(attn, Inv, Vp, Vals);

    // 5) out = vals @ Wo + bo
    proj_gemm<<<gProj, blk>>>(Vals, Wo, out, D_MODEL, bo);
}

// round 6
// speedup vs baseline: 1.3088x; 1.3088x over previous
#include <cuda_runtime.h>
#include <math.h>
#include <stdint.h>

#define S_LEN 4096
#define D_MODEL 1024
#define N_HEADS 16
#define D_HEAD 64
#define BK 32

// Scratch (allocation-free rule: __device__ globals)
__device__ float g_Qp[S_LEN * D_MODEL];
__device__ float g_Kp[S_LEN * D_MODEL];
__device__ float g_Vp[S_LEN * D_MODEL];
__device__ float g_vals[S_LEN * D_MODEL];
__device__ float g_inv[(size_t)N_HEADS * S_LEN];  // 1 / rowsum
__device__ float g_attn_fallback[(size_t)N_HEADS * S_LEN * S_LEN];

__device__ __forceinline__ float to_tf32(float x) {
    float y;
    asm("cvt.rna.tf32.f32 %0, %1;" : "=f"(y) : "f"(x));
    return y;
}

__device__ __forceinline__ void mma_tf32(float& d0, float& d1, float& d2, float& d3,
                                         float a0, float a1, float a2, float a3,
                                         float b0, float b1)
{
    uint32_t ua0 = __float_as_uint(a0), ua1 = __float_as_uint(a1);
    uint32_t ua2 = __float_as_uint(a2), ua3 = __float_as_uint(a3);
    uint32_t ub0 = __float_as_uint(b0), ub1 = __float_as_uint(b1);
    asm volatile(
        "mma.sync.aligned.m16n8k8.row.col.f32.tf32.tf32.f32 "
        "{%0,%1,%2,%3}, {%4,%5,%6,%7}, {%8,%9}, {%0,%1,%2,%3};"
        : "+f"(d0), "+f"(d1), "+f"(d2), "+f"(d3)
        : "r"(ua0), "r"(ua1), "r"(ua2), "r"(ua3), "r"(ub0), "r"(ub1));
}

// ---------------------------------------------------------------------------
// Projections: C = A @ B + bias, B row-major [K, N]. BM=BN=128, BK=32.
// ---------------------------------------------------------------------------
__global__ void __launch_bounds__(256, 2)
proj_gemm(const float* __restrict__ A,
          const float* __restrict__ B,
          float* __restrict__ C,
          int K, const float* __restrict__ bias)
{
    __shared__ __align__(16) float As[128][BK + 4];
    __shared__ __align__(16) float Bs[BK][128 + 4];

    const int m0 = blockIdx.y * 128;
    const int n0 = blockIdx.x * 128;
    const int tid = threadIdx.x;
    const int warp = tid >> 5;
    const int lane = tid & 31;
    const int gid = lane >> 2;
    const int tig = lane & 3;
    const int wm0 = (warp >> 1) * 32;
    const int wn0 = (warp & 1) * 64;

    float acc[2][8][4];
    #pragma unroll
    for (int mi = 0; mi < 2; mi++)
        #pragma unroll
        for (int ni = 0; ni < 8; ni++)
            #pragma unroll
            for (int j = 0; j < 4; j++) acc[mi][ni][j] = 0.f;

    for (int k0 = 0; k0 < K; k0 += BK) {
        #pragma unroll
        for (int i = 0; i < 4; i++) {
            int idx = tid + i * 256;
            int r = idx >> 3;
            int kq = (idx & 7) * 4;
            float4 f = *(const float4*)(A + (long)(m0 + r) * K + k0 + kq);
            *(float4*)&As[r][kq] = make_float4(to_tf32(f.x), to_tf32(f.y),
                                               to_tf32(f.z), to_tf32(f.w));
        }
        #pragma unroll
        for (int i = 0; i < 4; i++) {
            int idx = tid + i * 256;
            int kr = idx >> 5;
            int nq = (idx & 31) * 4;
            float4 f = *(const float4*)(B + (long)(k0 + kr) * D_MODEL + n0 + nq);
            *(float4*)&Bs[kr][nq] = make_float4(to_tf32(f.x), to_tf32(f.y),
                                                to_tf32(f.z), to_tf32(f.w));
        }
        __syncthreads();

        #pragma unroll
        for (int ks = 0; ks < BK; ks += 8) {
            float af[2][4];
            #pragma unroll
            for (int mi = 0; mi < 2; mi++) {
                af[mi][0] = As[wm0 + mi * 16 + gid][ks + tig];
                af[mi][1] = As[wm0 + mi * 16 + gid + 8][ks + tig];
                af[mi][2] = As[wm0 + mi * 16 + gid][ks + tig + 4];
                af[mi][3] = As[wm0 + mi * 16 + gid + 8][ks + tig + 4];
            }
            float bf[8][2];
            #pragma unroll
            for (int ni = 0; ni < 8; ni++) {
                bf[ni][0] = Bs[ks + tig][wn0 + ni * 8 + gid];
                bf[ni][1] = Bs[ks + tig + 4][wn0 + ni * 8 + gid];
            }
            #pragma unroll
            for (int mi = 0; mi < 2; mi++)
                #pragma unroll
                for (int ni = 0; ni < 8; ni++)
                    mma_tf32(acc[mi][ni][0], acc[mi][ni][1], acc[mi][ni][2], acc[mi][ni][3],
                             af[mi][0], af[mi][1], af[mi][2], af[mi][3],
                             bf[ni][0], bf[ni][1]);
        }
        __syncthreads();
    }

    #pragma unroll
    for (int mi = 0; mi < 2; mi++) {
        int r0 = m0 + wm0 + mi * 16 + gid;
        #pragma unroll
        for (int ni = 0; ni < 8; ni++) {
            int c = n0 + wn0 + ni * 8 + tig * 2;
            float b0 = bias[c], b1 = bias[c + 1];
            *(float2*)&C[(long)r0 * D_MODEL + c] =
                make_float2(acc[mi][ni][0] + b0, acc[mi][ni][1] + b1);
            *(float2*)&C[(long)(r0 + 8) * D_MODEL + c] =
                make_float2(acc[mi][ni][2] + b0, acc[mi][ni][3] + b1);
        }
    }
}

// ---------------------------------------------------------------------------
// Rowsum pass: for each (mb, h), recompute s = scale*Q@K^T over all columns,
// accumulate sum of exp(s) per row in registers, write inv = 1/sum.
// ---------------------------------------------------------------------------
__global__ void __launch_bounds__(256, 2)
rowsum_kernel(const float* __restrict__ Qp, const float* __restrict__ Kp,
              float* __restrict__ inv, float scale)
{
    extern __shared__ __align__(16) float sm[];
    float (*Qs)[D_HEAD + 4] = (float (*)[D_HEAD + 4])sm;
    float (*Ks)[D_HEAD + 4] = (float (*)[D_HEAD + 4])(sm + 128 * (D_HEAD + 4));
    __shared__ float red[2][128];

    const int mb = blockIdx.x, h = blockIdx.y;
    const float* Aq = Qp + (long)mb * 128 * D_MODEL + h * D_HEAD;

    const int tid = threadIdx.x;
    const int warp = tid >> 5;
    const int lane = tid & 31;
    const int gid = lane >> 2;
    const int tig = lane & 3;
    const int wm0 = (warp >> 1) * 32;
    const int wn = warp & 1;
    const int wn0 = wn * 64;

    #pragma unroll
    for (int i = 0; i < 8; i++) {
        int idx = tid + i * 256;
        int r = idx >> 4;
        int c4 = (idx & 15) * 4;
        float4 fq = *(const float4*)(Aq + (long)r * D_MODEL + c4);
        *(float4*)&Qs[r][c4] = make_float4(to_tf32(fq.x), to_tf32(fq.y),
                                           to_tf32(fq.z), to_tf32(fq.w));
    }

    float rp[2][2] = {{0.f, 0.f}, {0.f, 0.f}};

    for (int nb = 0; nb < S_LEN / 128; nb++) {
        const float* Bk = Kp + (long)nb * 128 * D_MODEL + h * D_HEAD;
        __syncthreads();
        #pragma unroll
        for (int i = 0; i < 8; i++) {
            int idx = tid + i * 256;
            int r = idx >> 4;
            int c4 = (idx & 15) * 4;
            float4 fk = *(const float4*)(Bk + (long)r * D_MODEL + c4);
            *(float4*)&Ks[r][c4] = make_float4(to_tf32(fk.x), to_tf32(fk.y),
                                               to_tf32(fk.z), to_tf32(fk.w));
        }
        __syncthreads();

        float acc[2][8][4];
        #pragma unroll
        for (int mi = 0; mi < 2; mi++)
            #pragma unroll
            for (int ni = 0; ni < 8; ni++)
                #pragma unroll
                for (int j = 0; j < 4; j++) acc[mi][ni][j] = 0.f;

        #pragma unroll
        for (int ks = 0; ks < D_HEAD; ks += 8) {
            float af[2][4];
            #pragma unroll
            for (int mi = 0; mi < 2; mi++) {
                af[mi][0] = Qs[wm0 + mi * 16 + gid][ks + tig];
                af[mi][1] = Qs[wm0 + mi * 16 + gid + 8][ks + tig];
                af[mi][2] = Qs[wm0 + mi * 16 + gid][ks + tig + 4];
                af[mi][3] = Qs[wm0 + mi * 16 + gid + 8][ks + tig + 4];
            }
            float bf[8][2];
            #pragma unroll
            for (int ni = 0; ni < 8; ni++) {
                bf[ni][0] = Ks[wn0 + ni * 8 + gid][ks + tig];
                bf[ni][1] = Ks[wn0 + ni * 8 + gid][ks + tig + 4];
            }
            #pragma unroll
            for (int mi = 0; mi < 2; mi++)
                #pragma unroll
                for (int ni = 0; ni < 8; ni++)
                    mma_tf32(acc[mi][ni][0], acc[mi][ni][1], acc[mi][ni][2], acc[mi][ni][3],
                             af[mi][0], af[mi][1], af[mi][2], af[mi][3],
                             bf[ni][0], bf[ni][1]);
        }

        #pragma unroll
        for (int mi = 0; mi < 2; mi++)
            #pragma unroll
            for (int ni = 0; ni < 8; ni++) {
                rp[mi][0] += __expf(scale * acc[mi][ni][0]) + __expf(scale * acc[mi][ni][1]);
                rp[mi][1] += __expf(scale * acc[mi][ni][2]) + __expf(scale * acc[mi][ni][3]);
            }
    }

    #pragma unroll
    for (int mi = 0; mi < 2; mi++)
        #pragma unroll
        for (int hh = 0; hh < 2; hh++) {
            rp[mi][hh] += __shfl_xor_sync(0xffffffffu, rp[mi][hh], 1);
            rp[mi][hh] += __shfl_xor_sync(0xffffffffu, rp[mi][hh], 2);
        }
    if (tig == 0) {
        #pragma unroll
        for (int mi = 0; mi < 2; mi++)
            #pragma unroll
            for (int hh = 0; hh < 2; hh++)
                red[wn][wm0 + mi * 16 + gid + 8 * hh] = rp[mi][hh];
    }
    __syncthreads();
    if (tid < 128) {
        long row = (long)h * S_LEN + mb * 128 + tid;
        inv[row] = 1.0f / (red[0][tid] + red[1][tid]);
    }
}

// ---------------------------------------------------------------------------
// Fused attention: for each (mb, h), loop over 64-wide K/V tiles:
//   S = Q@K^T (mma), p = exp(scale*s)*inv[row] -> staged in smem Ps,
//   O += Ps@V (mma), attn written once via coalesced float4 from Ps.
// ---------------------------------------------------------------------------
__global__ void __launch_bounds__(256, 2)
fused_attn_kernel(const float* __restrict__ Qp, const float* __restrict__ Kp,
                  const float* __restrict__ Vp, const float* __restrict__ invp,
                  float* __restrict__ attn, float* __restrict__ vals, float scale)
{
    extern __shared__ __align__(16) float sm[];
    const int LD = D_HEAD + 4;
    float (*Qs)[D_HEAD + 4] = (float (*)[D_HEAD + 4])sm;
    float (*Ks)[D_HEAD + 4] = (float (*)[D_HEAD + 4])(sm + 128 * LD);
    float (*Vs)[D_HEAD + 4] = (float (*)[D_HEAD + 4])(sm + 192 * LD);
    float (*Ps)[D_HEAD + 4] = (float (*)[D_HEAD + 4])(sm + 256 * LD);
    float* invs = sm + 384 * LD;

    const int mb = blockIdx.x, h = blockIdx.y;
    const float* Aq = Qp + (long)mb * 128 * D_MODEL + h * D_HEAD;
    const long attn_row0 = (long)h * S_LEN + mb * 128;

    const int tid = threadIdx.x;
    const int warp = tid >> 5;
    const int lane = tid & 31;
    const int gid = lane >> 2;
    const int tig = lane & 3;
    const int wm0 = (warp >> 1) * 32;
    const int wn0 = (warp & 1) * 32;

    // Stage Q (tf32) and inv
    #pragma unroll
    for (int i = 0; i < 8; i++) {
        int idx = tid + i * 256;
        int r = idx >> 4;
        int c4 = (idx & 15) * 4;
        float4 fq = *(const float4*)(Aq + (long)r * D_MODEL + c4);
        *(float4*)&Qs[r][c4] = make_float4(to_tf32(fq.x), to_tf32(fq.y),
                                           to_tf32(fq.z), to_tf32(fq.w));
    }
    if (tid < 128) invs[tid] = invp[attn_row0 + tid];

    float oacc[2][4][4];
    #pragma unroll
    for (int mi = 0; mi < 2; mi++)
        #pragma unroll
        for (int ni = 0; ni < 4; ni++)
            #pragma unroll
            for (int j = 0; j < 4; j++) oacc[mi][ni][j] = 0.f;

    for (int nb = 0; nb < S_LEN / D_HEAD; nb++) {
        __syncthreads();   // protect Ks/Vs/Ps from previous iteration users
        // Load K, V 64x64 tiles
        #pragma unroll
        for (int i = 0; i < 4; i++) {
            int idx = tid + i * 256;
            int r = idx >> 4;
            int c4 = (idx & 15) * 4;
            const float* gk = Kp + (long)(nb * 64 + r) * D_MODEL + h * D_HEAD + c4;
            float4 fk = *(const float4*)gk;
            *(float4*)&Ks[r][c4] = make_float4(to_tf32(fk.x), to_tf32(fk.y),
                                               to_tf32(fk.z), to_tf32(fk.w));
            const float* gv = Vp + (long)(nb * 64 + r) * D_MODEL + h * D_HEAD + c4;
            float4 fv = *(const float4*)gv;
            *(float4*)&Vs[r][c4] = make_float4(to_tf32(fv.x), to_tf32(fv.y),
                                               to_tf32(fv.z), to_tf32(fv.w));
        }
        __syncthreads();

        // S = Q @ K^T  (128 x 64)
        float acc[2][4][4];
        #pragma unroll
        for (int mi = 0; mi < 2; mi++)
            #pragma unroll
            for (int ni = 0; ni < 4; ni++)
                #pragma unroll
                for (int j = 0; j < 4; j++) acc[mi][ni][j] = 0.f;

        #pragma unroll
        for (int ks = 0; ks < D_HEAD; ks += 8) {
            float af[2][4];
            #pragma unroll
            for (int mi = 0; mi < 2; mi++) {
                af[mi][0] = Qs[wm0 + mi * 16 + gid][ks + tig];
                af[mi][1] = Qs[wm0 + mi * 16 + gid + 8][ks + tig];
                af[mi][2] = Qs[wm0 + mi * 16 + gid][ks + tig + 4];
                af[mi][3] = Qs[wm0 + mi * 16 + gid + 8][ks + tig + 4];
            }
            float bf[4][2];
            #pragma unroll
            for (int ni = 0; ni < 4; ni++) {
                bf[ni][0] = Ks[wn0 + ni * 8 + gid][ks + tig];
                bf[ni][1] = Ks[wn0 + ni * 8 + gid][ks + tig + 4];
            }
            #pragma unroll
            for (int mi = 0; mi < 2; mi++)
                #pragma unroll
                for (int ni = 0; ni < 4; ni++)
                    mma_tf32(acc[mi][ni][0], acc[mi][ni][1], acc[mi][ni][2], acc[mi][ni][3],
                             af[mi][0], af[mi][1], af[mi][2], af[mi][3],
                             bf[ni][0], bf[ni][1]);
        }

        // p = exp(scale*s) * inv -> Ps
        #pragma unroll
        for (int mi = 0; mi < 2; mi++) {
            int r = wm0 + mi * 16 + gid;
            float iv0 = invs[r], iv1 = invs[r + 8];
            #pragma unroll
            for (int ni = 0; ni < 4; ni++) {
                int c = wn0 + ni * 8 + tig * 2;
                *(float2*)&Ps[r][c] =
                    make_float2(__expf(scale * acc[mi][ni][0]) * iv0,
                                __expf(scale * acc[mi][ni][1]) * iv0);
                *(float2*)&Ps[r + 8][c] =
                    make_float2(__expf(scale * acc[mi][ni][2]) * iv1,
                                __expf(scale * acc[mi][ni][3]) * iv1);
            }
        }
        __syncthreads();

        // O += Ps @ Vs  (128 x 64, K=64)
        #pragma unroll
        for (int ks = 0; ks < D_HEAD; ks += 8) {
            float af[2][4];
            #pragma unroll
            for (int mi = 0; mi < 2; mi++) {
                af[mi][0] = Ps[wm0 + mi * 16 + gid][ks + tig];
                af[mi][1] = Ps[wm0 + mi * 16 + gid + 8][ks + tig];
                af[mi][2] = Ps[wm0 + mi * 16 + gid][ks + tig + 4];
                af[mi][3] = Ps[wm0 + mi * 16 + gid + 8][ks + tig + 4];
            }
            float bf[4][2];
            #pragma unroll
            for (int ni = 0; ni < 4; ni++) {
                bf[ni][0] = Vs[ks + tig][wn0 + ni * 8 + gid];
                bf[ni][1] = Vs[ks + tig + 4][wn0 + ni * 8 + gid];
            }
            #pragma unroll
            for (int mi = 0; mi < 2; mi++)
                #pragma unroll
                for (int ni = 0; ni < 4; ni++)
                    mma_tf32(oacc[mi][ni][0], oacc[mi][ni][1], oacc[mi][ni][2], oacc[mi][ni][3],
                             af[mi][0], af[mi][1], af[mi][2], af[mi][3],
                             bf[ni][0], bf[ni][1]);
        }

        // Write attn tile from Ps, fully coalesced float4 (128x64 = 2048 float4s)
        #pragma unroll
        for (int i = 0; i < 8; i++) {
            int idx = tid + i * 256;
            int r = idx >> 4;
            int c4 = (idx & 15) * 4;
            *(float4*)&attn[(attn_row0 + r) * S_LEN + nb * 64 + c4] =
                *(const float4*)&Ps[r][c4];
        }
    }

    // Epilogue: write O
    #pragma unroll
    for (int mi = 0; mi < 2; mi++) {
        int r0 = mb * 128 + wm0 + mi * 16 + gid;
        #pragma unroll
        for (int ni = 0; ni < 4; ni++) {
            int c = h * D_HEAD + wn0 + ni * 8 + tig * 2;
            *(float2*)&vals[(long)r0 * D_MODEL + c] =
                make_float2(oacc[mi][ni][0], oacc[mi][ni][1]);
            *(float2*)&vals[(long)(r0 + 8) * D_MODEL + c] =
                make_float2(oacc[mi][ni][2], oacc[mi][ni][3]);
        }
    }
}

extern "C" void kernel_launch(void* const* d_in, const int* in_sizes, int n_in,
                              void* d_out, int out_size)
{
    const float* q  = (const float*)d_in[0];
    const float* k  = (const float*)d_in[1];
    const float* v  = (const float*)d_in[2];
    const float* Wq = (const float*)d_in[3];
    const float* bq = (const float*)d_in[4];
    const float* Wk = (const float*)d_in[5];
    const float* bk = (const float*)d_in[6];
    const float* Wv = (const float*)d_in[7];
    const float* bv = (const float*)d_in[8];
    const float* Wo = (const float*)d_in[9];
    const float* bo = (const float*)d_in[10];

    float* out = (float*)d_out;

    float *Qp, *Kp, *Vp, *Vals, *Inv, *attn_fb;
    cudaGetSymbolAddress((void**)&Qp,   g_Qp);
    cudaGetSymbolAddress((void**)&Kp,   g_Kp);
    cudaGetSymbolAddress((void**)&Vp,   g_Vp);
    cudaGetSymbolAddress((void**)&Vals, g_vals);
    cudaGetSymbolAddress((void**)&Inv,  g_inv);
    cudaGetSymbolAddress((void**)&attn_fb, g_attn_fallback);

    const long OUT_ELEMS  = (long)S_LEN * D_MODEL;
    const long ATTN_ELEMS = (long)N_HEADS * S_LEN * S_LEN;
    float* attn = ((long)out_size >= OUT_ELEMS + ATTN_ELEMS)
                      ? (out + OUT_ELEMS)
                      : attn_fb;

    const int LD = D_HEAD + 4;
    const int ROWSUM_SMEM = 2 * 128 * LD * (int)sizeof(float);           // ~69.6 KB
    const int FUSED_SMEM  = (384 * LD + 128) * (int)sizeof(float);       // ~105 KB
    static bool attr_done = false;
    if (!attr_done) {
        cudaFuncSetAttribute(rowsum_kernel,
                             cudaFuncAttributeMaxDynamicSharedMemorySize, ROWSUM_SMEM);
        cudaFuncSetAttribute(fused_attn_kernel,
                             cudaFuncAttributeMaxDynamicSharedMemorySize, FUSED_SMEM);
        attr_done = true;
    }

    dim3 blk(256);
    const float scale = 1.0f / sqrtf((float)D_HEAD);

    // 1) Projections
    dim3 gProj(D_MODEL / 128, S_LEN / 128, 1);
    proj_gemm<<<gProj, blk>>>(q, Wq, Qp, D_MODEL, bq);
    proj_gemm<<<gProj, blk>>>(k, Wk, Kp, D_MODEL, bk);
    proj_gemm<<<gProj, blk>>>(v, Wv, Vp, D_MODEL, bv);

    // 2) Row sums -> inv
    dim3 gRS(S_LEN / 128, N_HEADS);
    rowsum_kernel<<<gRS, blk, ROWSUM_SMEM>>>(Qp, Kp, Inv, scale);

    // 3) Fused: recompute scores, normalize, write attn once, O = P@V
    dim3 gF(S_LEN / 128, N_HEADS);
    fused_attn_kernel<<<gF, blk, FUSED_SMEM>>>(Qp, Kp, Vp, Inv, attn, Vals, scale);

    // 4) out = vals @ Wo + bo
    proj_gemm<<<gProj, blk>>>(Vals, Wo, out, D_MODEL, bo);
}